// round 2
// baseline (speedup 1.0000x reference)
#include <cuda_runtime.h>
#include <cuda_bf16.h>
#include <math.h>

#define NN 50000
#define CC 128
#define EE 800000

// ---------------- scratch (static device globals; no allocation) ----------
__device__ float g_m[NN * CC];        // state @ W_lin^T
__device__ float g_prop[NN * CC];     // segment-sum result
__device__ float g_sA[NN * CC];       // state ping
__device__ float g_sB[NN * CC];       // state pong
__device__ float g_gi[NN * 3 * CC];   // input gates
__device__ float g_gh[NN * 3 * CC];   // hidden gates
__device__ int   g_cnt[NN];           // degree counts / fill cursor
__device__ int   g_rowptr[NN + 1];    // CSR row pointers (by dst)
__device__ int   g_perm[EE];          // src node per CSR slot
__device__ int   g_bsum[64];          // scan block sums

// ---------------- small utility kernels -----------------------------------
__global__ void zero_int(int* p, int n) {
    int i = blockIdx.x * blockDim.x + threadIdx.x;
    if (i < n) p[i] = 0;
}

__global__ void count_k(const int* __restrict__ dst, int* __restrict__ cnt) {
    int e = blockIdx.x * blockDim.x + threadIdx.x;
    if (e < EE) {
        int d = dst[e];
        d = min(max(d, 0), NN - 1);
        atomicAdd(&cnt[d], 1);
    }
}

// Hillis-Steele inclusive scan per 1024-block; writes exclusive result
__global__ void scan_block(const int* __restrict__ cnt, int* __restrict__ excl,
                           int* __restrict__ bsum, int n) {
    __shared__ int sm[1024];
    int t = threadIdx.x;
    int g = blockIdx.x * 1024 + t;
    int v = (g < n) ? cnt[g] : 0;
    sm[t] = v;
    __syncthreads();
    for (int off = 1; off < 1024; off <<= 1) {
        int tv = 0;
        if (t >= off) tv = sm[t - off];
        __syncthreads();
        if (t >= off) sm[t] += tv;
        __syncthreads();
    }
    if (g < n) excl[g] = sm[t] - v;
    if (t == 1023) bsum[blockIdx.x] = sm[1023];
}

__global__ void scan_sums(int* bsum, int nb) {
    int run = 0;
    for (int i = 0; i < nb; i++) { int t = bsum[i]; bsum[i] = run; run += t; }
}

__global__ void add_off(int* __restrict__ rowptr, const int* __restrict__ bsum, int n) {
    int g = blockIdx.x * blockDim.x + threadIdx.x;
    if (g < n) rowptr[g] += bsum[g >> 10];
    if (g == 0) rowptr[n] = EE;
}

__global__ void fill_k(const int* __restrict__ src, const int* __restrict__ dst,
                       const int* __restrict__ rowptr, int* __restrict__ cur,
                       int* __restrict__ perm) {
    int e = blockIdx.x * blockDim.x + threadIdx.x;
    if (e < EE) {
        int d = dst[e];
        d = min(max(d, 0), NN - 1);
        int s = src[e];
        s = min(max(s, 0), NN - 1);
        int pos = rowptr[d] + atomicAdd(&cur[d], 1);
        if (pos >= 0 && pos < EE) perm[pos] = s;
    }
}

// ---------------- GEMM: Y[nrows,M] = X[nrows,128] @ W[M,128]^T (+bias) ----
// BM=128 rows, BN=64 cols per block, 256 threads, 8x4 micro-tile, full K=128 in smem.
#define SMEM_GEMM ((128 * 128 + 64 * 129) * 4)

__global__ __launch_bounds__(256)
void gemm_xwt(const float* __restrict__ X, const float* __restrict__ W,
              const float* __restrict__ bias, float* __restrict__ Y,
              int nrows, int M) {
    extern __shared__ float shbuf[];
    float* Xs = shbuf;                 // [128][128]  Xs[r][k]
    float* Ws = shbuf + 128 * 128;     // [64][129]   Ws[c][k]
    const int WSS = 129;

    int row0 = blockIdx.x * 128;
    int col0 = blockIdx.y * 64;
    int tid = threadIdx.x;

    // load X tile (128x128 floats = 4096 float4, 16 per thread), zero-pad OOB rows
    {
        const float4* Xg = (const float4*)X;
        #pragma unroll
        for (int i = 0; i < 16; i++) {
            int idx = tid + i * 256;       // 0..4095
            int r = idx >> 5;
            int c4 = idx & 31;
            float4 v = make_float4(0.f, 0.f, 0.f, 0.f);
            if (row0 + r < nrows) v = Xg[(size_t)(row0 + r) * 32 + c4];
            *(float4*)&Xs[r * 128 + c4 * 4] = v;
        }
    }
    // load W tile (64x128 floats = 2048 float4, 8 per thread) into padded rows
    {
        const float4* Wg = (const float4*)W;
        #pragma unroll
        for (int i = 0; i < 8; i++) {
            int idx = tid + i * 256;       // 0..2047
            int c = idx >> 5;
            int k4 = idx & 31;
            float4 v = Wg[(size_t)(col0 + c) * 32 + k4];
            Ws[c * WSS + k4 * 4 + 0] = v.x;
            Ws[c * WSS + k4 * 4 + 1] = v.y;
            Ws[c * WSS + k4 * 4 + 2] = v.z;
            Ws[c * WSS + k4 * 4 + 3] = v.w;
        }
    }
    __syncthreads();

    int tx = tid & 15;   // -> cols col0 + 4*tx + v
    int ty = tid >> 4;   // -> rows row0 + 8*ty + u

    float acc[8][4];
    #pragma unroll
    for (int u = 0; u < 8; u++)
        #pragma unroll
        for (int v = 0; v < 4; v++) acc[u][v] = 0.f;

    const float* xb = &Xs[(8 * ty) * 128];
    const float* wb = &Ws[(4 * tx) * WSS];

    #pragma unroll 8
    for (int k = 0; k < 128; k += 4) {
        float4 xv[8];
        #pragma unroll
        for (int u = 0; u < 8; u++) xv[u] = *(const float4*)&xb[u * 128 + k];
        float wv[4][4];
        #pragma unroll
        for (int v = 0; v < 4; v++) {
            wv[v][0] = wb[v * WSS + k + 0];
            wv[v][1] = wb[v * WSS + k + 1];
            wv[v][2] = wb[v * WSS + k + 2];
            wv[v][3] = wb[v * WSS + k + 3];
        }
        #pragma unroll
        for (int u = 0; u < 8; u++) {
            #pragma unroll
            for (int v = 0; v < 4; v++) {
                acc[u][v] += xv[u].x * wv[v][0];
                acc[u][v] += xv[u].y * wv[v][1];
                acc[u][v] += xv[u].z * wv[v][2];
                acc[u][v] += xv[u].w * wv[v][3];
            }
        }
    }

    float4 b4 = make_float4(0.f, 0.f, 0.f, 0.f);
    if (bias) b4 = *(const float4*)&bias[col0 + 4 * tx];

    #pragma unroll
    for (int u = 0; u < 8; u++) {
        int r = row0 + 8 * ty + u;
        if (r < nrows) {
            float4 o;
            o.x = acc[u][0] + b4.x;
            o.y = acc[u][1] + b4.y;
            o.z = acc[u][2] + b4.z;
            o.w = acc[u][3] + b4.w;
            *(float4*)&Y[(size_t)r * M + col0 + 4 * tx] = o;
        }
    }
}

// ---------------- aggregation: prop[i,:] = sum over in-edges m[src,:] -----
__global__ void aggregate(const float* __restrict__ m, const int* __restrict__ rowptr,
                          const int* __restrict__ perm, float* __restrict__ prop) {
    int i = blockIdx.x;
    int c = threadIdx.x;
    int s0 = rowptr[i], s1 = rowptr[i + 1];
    float a0 = 0.f, a1 = 0.f, a2 = 0.f, a3 = 0.f;
    int e = s0;
    for (; e + 3 < s1; e += 4) {
        int p0 = perm[e], p1 = perm[e + 1], p2 = perm[e + 2], p3 = perm[e + 3];
        a0 += m[p0 * 128 + c];
        a1 += m[p1 * 128 + c];
        a2 += m[p2 * 128 + c];
        a3 += m[p3 * 128 + c];
    }
    for (; e < s1; e++) a0 += m[perm[e] * 128 + c];
    prop[i * 128 + c] = (a0 + a1) + (a2 + a3);
}

// ---------------- GRU elementwise ------------------------------------------
__global__ void gru_k(const float* __restrict__ gi, const float* __restrict__ gh,
                      const float* __restrict__ h, float* __restrict__ out, int n) {
    int idx = blockIdx.x * blockDim.x + threadIdx.x;
    if (idx >= n) return;
    int i = idx >> 7;
    int c = idx & 127;
    const float* gir = gi + (size_t)i * 384;
    const float* ghr = gh + (size_t)i * 384;
    float ir = gir[c], iz = gir[c + 128], in_ = gir[c + 256];
    float hr = ghr[c], hz = ghr[c + 128], hn = ghr[c + 256];
    float r = 1.f / (1.f + expf(-(ir + hr)));
    float z = 1.f / (1.f + expf(-(iz + hz)));
    float nval = tanhf(in_ + r * hn);
    out[idx] = (1.f - z) * nval + z * h[idx];
}

// ---------------- launcher --------------------------------------------------
extern "C" void kernel_launch(void* const* d_in, const int* in_sizes, int n_in,
                              void* d_out, int out_size) {
    const float* x     = (const float*)d_in[0];
    const int*   ei    = (const int*)d_in[1];   // JAX default x64-disabled: int32
    const float* W_lin = (const float*)d_in[2];
    const float* W_ih  = (const float*)d_in[3];
    const float* W_hh  = (const float*)d_in[4];
    const float* b_ih  = (const float*)d_in[5];
    const float* b_hh  = (const float*)d_in[6];
    float* out = (float*)d_out;

    const int* src = ei;
    const int* dst = ei + EE;

    float *m_, *prop_, *sA_, *sB_, *gi_, *gh_;
    int *cnt_, *rp_, *perm_, *bsum_;
    cudaGetSymbolAddress((void**)&m_,    g_m);
    cudaGetSymbolAddress((void**)&prop_, g_prop);
    cudaGetSymbolAddress((void**)&sA_,   g_sA);
    cudaGetSymbolAddress((void**)&sB_,   g_sB);
    cudaGetSymbolAddress((void**)&gi_,   g_gi);
    cudaGetSymbolAddress((void**)&gh_,   g_gh);
    cudaGetSymbolAddress((void**)&cnt_,  g_cnt);
    cudaGetSymbolAddress((void**)&rp_,   g_rowptr);
    cudaGetSymbolAddress((void**)&perm_, g_perm);
    cudaGetSymbolAddress((void**)&bsum_, g_bsum);

    cudaFuncSetAttribute(gemm_xwt, cudaFuncAttributeMaxDynamicSharedMemorySize, SMEM_GEMM);

    const int NB_SCAN = (NN + 1023) / 1024;   // 49

    // ---- build CSR (edge structure fixed across steps) ----
    zero_int <<<(NN + 255) / 256, 256>>>(cnt_, NN);
    count_k  <<<(EE + 255) / 256, 256>>>(dst, cnt_);
    scan_block<<<NB_SCAN, 1024>>>(cnt_, rp_, bsum_, NN);
    scan_sums <<<1, 1>>>(bsum_, NB_SCAN);
    add_off   <<<(NN + 255) / 256, 256>>>(rp_, bsum_, NN);
    zero_int  <<<(NN + 255) / 256, 256>>>(cnt_, NN);
    fill_k    <<<(EE + 255) / 256, 256>>>(src, dst, rp_, cnt_, perm_);

    // ---- 3 propagation steps ----
    dim3 g128((NN + 127) / 128, 128 / 64);
    dim3 g384((NN + 127) / 128, 384 / 64);

    const float* sin = x;
    for (int step = 0; step < 3; step++) {
        float* sout = (step == 2) ? out : ((step == 0) ? sA_ : sB_);

        gemm_xwt<<<g128, 256, SMEM_GEMM>>>(sin, W_lin, nullptr, m_, NN, 128);
        aggregate<<<NN, 128>>>(m_, rp_, perm_, prop_);
        gemm_xwt<<<g384, 256, SMEM_GEMM>>>(prop_, W_ih, b_ih, gi_, NN, 384);
        gemm_xwt<<<g384, 256, SMEM_GEMM>>>(sin, W_hh, b_hh, gh_, NN, 384);
        gru_k<<<(NN * CC + 255) / 256, 256>>>(gi_, gh_, sin, sout, NN * CC);

        sin = sout;
    }
}